// round 1
// baseline (speedup 1.0000x reference)
#include <cuda_runtime.h>

// Problem constants
#define BD      2
#define SEQ     2048
#define DM      768
#define NH      12
#define DK      64
#define MROWS   (BD*SEQ)          // 4096
#define ATT_SCALE 0.125f          // 1/sqrt(64)
#define FLATROWS (BD*NH*SEQ)      // 49152 rows of 64 (softmax rows)

// Scratch (device globals: no allocation allowed)
__device__ float g_Q[MROWS*DM];
__device__ float g_K[MROWS*DM];
__device__ float g_V[MROWS*DM];
__device__ float g_T[MROWS*DM];
__device__ float g_M[MROWS*DM];

// ---------------------------------------------------------------------------
// GEMM: C[M,N] = A[M,K] @ W^T + bias, W is [N,K] row-major (torch Linear)
// Tiles: 128x128x16, 256 threads, 8x8 per thread.
// ---------------------------------------------------------------------------
#define BM 128
#define BN 128
#define BK 16
#define TM 8
#define TN 8

__global__ void __launch_bounds__(256) gemm_bias_kernel(
    const float* __restrict__ A,
    const float* __restrict__ W,
    const float* __restrict__ bias,
    float* __restrict__ C,
    int M, int N, int K)
{
    __shared__ float As[BM][BK];      // natural [row][k]
    __shared__ float Bs[BK][BN];      // transposed: Bs[k][n] = W[n][k]

    const int tid = threadIdx.x;
    const int tx  = tid & 15;         // 0..15 -> N direction
    const int ty  = tid >> 4;         // 0..15 -> M direction
    const int row0 = blockIdx.y * BM;
    const int col0 = blockIdx.x * BN;

    float acc[TM][TN];
    #pragma unroll
    for (int i = 0; i < TM; i++)
        #pragma unroll
        for (int j = 0; j < TN; j++) acc[i][j] = 0.0f;

    for (int k0 = 0; k0 < K; k0 += BK) {
        // Load A tile: scalar, coalesced global, conflict-free shared writes
        #pragma unroll
        for (int i = tid; i < BM*BK; i += 256) {
            int r = i >> 4, c = i & 15;
            As[r][c] = A[(row0 + r) * K + k0 + c];
        }
        // Load W tile transposed: float4 global reads, scalar shared writes
        #pragma unroll
        for (int i = tid; i < BN*(BK/4); i += 256) {   // 512 float4
            int n  = i >> 2;
            int c4 = (i & 3) * 4;
            float4 w4 = *reinterpret_cast<const float4*>(
                &W[(col0 + n) * K + k0 + c4]);
            Bs[c4+0][n] = w4.x;
            Bs[c4+1][n] = w4.y;
            Bs[c4+2][n] = w4.z;
            Bs[c4+3][n] = w4.w;
        }
        __syncthreads();

        #pragma unroll
        for (int kk = 0; kk < BK; kk++) {
            float a[TM], b[TN];
            #pragma unroll
            for (int i = 0; i < TM; i++) a[i] = As[ty*TM + i][kk];
            float4 b0 = *reinterpret_cast<const float4*>(&Bs[kk][tx*TN]);
            float4 b1 = *reinterpret_cast<const float4*>(&Bs[kk][tx*TN + 4]);
            b[0]=b0.x; b[1]=b0.y; b[2]=b0.z; b[3]=b0.w;
            b[4]=b1.x; b[5]=b1.y; b[6]=b1.z; b[7]=b1.w;
            #pragma unroll
            for (int i = 0; i < TM; i++)
                #pragma unroll
                for (int j = 0; j < TN; j++)
                    acc[i][j] += a[i] * b[j];
        }
        __syncthreads();
    }

    #pragma unroll
    for (int i = 0; i < TM; i++) {
        int r = row0 + ty*TM + i;
        #pragma unroll
        for (int j = 0; j < TN; j++) {
            int c = col0 + tx*TN + j;
            C[r * N + c] = acc[i][j] + bias[c];
        }
    }
}

// ---------------------------------------------------------------------------
// Fused attention: per (b,h) block (2048x64 Q/K/V slabs, contiguous due to
// the reshape-view quirk): T = SCALE * (Q @ K^T) @ V, streamed over t-tiles.
// Block: 64 s-rows, 256 threads, each thread 4x4 of the 64x64 output.
// ---------------------------------------------------------------------------
#define KT_LD 68   // padded stride for transposed K tile (16B-aligned, low conflict)

__global__ void __launch_bounds__(256) attn_kernel(
    const float* __restrict__ Q,
    const float* __restrict__ K,
    const float* __restrict__ V,
    float* __restrict__ T)
{
    extern __shared__ float sm[];
    float* Qs = sm;                       // [64][64]
    float* Kt = Qs + 64*64;               // [64][KT_LD]  Kt[d][j] = K[t0+j][d]
    float* Vs = Kt + 64*KT_LD;            // [64][64]
    float* Ss = Vs + 64*64;               // [64][64]

    const int tid = threadIdx.x;
    const int tx  = tid & 15;             // j direction
    const int ty  = tid >> 4;             // i direction
    const int bh  = blockIdx.y;           // b*NH + h
    const int s0  = blockIdx.x * 64;
    const int base = bh * (SEQ * DK);     // contiguous 2048x64 slab

    const float* Qb = Q + base;
    const float* Kb = K + base;
    const float* Vb = V + base;

    // Q tile is a flat contiguous 64x64 copy
    #pragma unroll
    for (int i = tid*4; i < 64*64; i += 256*4)
        *reinterpret_cast<float4*>(&Qs[i]) =
            *reinterpret_cast<const float4*>(&Qb[s0*DK + i]);

    float acc[4][4];
    #pragma unroll
    for (int i = 0; i < 4; i++)
        #pragma unroll
        for (int j = 0; j < 4; j++) acc[i][j] = 0.0f;

    for (int t0 = 0; t0 < SEQ; t0 += 64) {
        // K tile transposed into shared (coalesced global reads)
        #pragma unroll
        for (int i = tid; i < 64*64; i += 256) {
            int j = i >> 6, d = i & 63;
            Kt[d*KT_LD + j] = Kb[(t0 + j) * DK + d];
        }
        // V tile flat copy
        #pragma unroll
        for (int i = tid*4; i < 64*64; i += 256*4)
            *reinterpret_cast<float4*>(&Vs[i]) =
                *reinterpret_cast<const float4*>(&Vb[t0*DK + i]);
        __syncthreads();

        // stage 1: Ss = Qs @ Kt (64x64 scores)
        float sv[4][4];
        #pragma unroll
        for (int i = 0; i < 4; i++)
            #pragma unroll
            for (int j = 0; j < 4; j++) sv[i][j] = 0.0f;

        #pragma unroll 8
        for (int d = 0; d < 64; d++) {
            float qa[4];
            #pragma unroll
            for (int ii = 0; ii < 4; ii++) qa[ii] = Qs[(ty*4+ii)*64 + d];
            float4 k4 = *reinterpret_cast<const float4*>(&Kt[d*KT_LD + tx*4]);
            float kb[4] = {k4.x, k4.y, k4.z, k4.w};
            #pragma unroll
            for (int ii = 0; ii < 4; ii++)
                #pragma unroll
                for (int jj = 0; jj < 4; jj++)
                    sv[ii][jj] += qa[ii] * kb[jj];
        }
        #pragma unroll
        for (int ii = 0; ii < 4; ii++) {
            float4 s4 = make_float4(sv[ii][0], sv[ii][1], sv[ii][2], sv[ii][3]);
            *reinterpret_cast<float4*>(&Ss[(ty*4+ii)*64 + tx*4]) = s4;
        }
        __syncthreads();

        // stage 2: acc += Ss @ Vs
        #pragma unroll 8
        for (int t = 0; t < 64; t++) {
            float sa[4];
            #pragma unroll
            for (int ii = 0; ii < 4; ii++) sa[ii] = Ss[(ty*4+ii)*64 + t];
            float4 v4 = *reinterpret_cast<const float4*>(&Vs[t*64 + tx*4]);
            float vb[4] = {v4.x, v4.y, v4.z, v4.w};
            #pragma unroll
            for (int ii = 0; ii < 4; ii++)
                #pragma unroll
                for (int jj = 0; jj < 4; jj++)
                    acc[ii][jj] += sa[ii] * vb[jj];
        }
        __syncthreads();
    }

    #pragma unroll
    for (int ii = 0; ii < 4; ii++) {
        int s = s0 + ty*4 + ii;
        float4 o4 = make_float4(acc[ii][0]*ATT_SCALE, acc[ii][1]*ATT_SCALE,
                                acc[ii][2]*ATT_SCALE, acc[ii][3]*ATT_SCALE);
        *reinterpret_cast<float4*>(&T[base + s*DK + tx*4]) = o4;
    }
}

#define ATTN_SMEM ((64*64*3 + 64*KT_LD) * (int)sizeof(float))

// ---------------------------------------------------------------------------
// Softmax over the last dk=64 axis (the faithful quirk). One warp per row.
// ---------------------------------------------------------------------------
__global__ void __launch_bounds__(256) softmax64_kernel(
    const float* __restrict__ T, float* __restrict__ Mo)
{
    int warp = (blockIdx.x * blockDim.x + threadIdx.x) >> 5;
    int lane = threadIdx.x & 31;
    if (warp >= FLATROWS) return;
    const float* row = T + (size_t)warp * 64;
    float v0 = row[lane], v1 = row[lane + 32];
    float mx = fmaxf(v0, v1);
    #pragma unroll
    for (int o = 16; o > 0; o >>= 1) mx = fmaxf(mx, __shfl_xor_sync(0xffffffffu, mx, o));
    float e0 = __expf(v0 - mx), e1 = __expf(v1 - mx);
    float sum = e0 + e1;
    #pragma unroll
    for (int o = 16; o > 0; o >>= 1) sum += __shfl_xor_sync(0xffffffffu, sum, o);
    float inv = 1.0f / sum;
    Mo[(size_t)warp*64 + lane]      = e0 * inv;
    Mo[(size_t)warp*64 + lane + 32] = e1 * inv;
}

// ---------------------------------------------------------------------------
// Launch
// ---------------------------------------------------------------------------
extern "C" void kernel_launch(void* const* d_in, const int* in_sizes, int n_in,
                              void* d_out, int out_size)
{
    const float* x  = (const float*)d_in[0];
    const float* Wq = (const float*)d_in[1];
    const float* bq = (const float*)d_in[2];
    const float* Wk = (const float*)d_in[3];
    const float* bk = (const float*)d_in[4];
    const float* Wv = (const float*)d_in[5];
    const float* bv = (const float*)d_in[6];
    const float* Wo = (const float*)d_in[7];
    const float* bo = (const float*)d_in[8];
    const float* Wf = (const float*)d_in[9];
    const float* bf = (const float*)d_in[10];
    float* out = (float*)d_out;

    float *gQ, *gK, *gV, *gT, *gM;
    cudaGetSymbolAddress((void**)&gQ, g_Q);
    cudaGetSymbolAddress((void**)&gK, g_K);
    cudaGetSymbolAddress((void**)&gV, g_V);
    cudaGetSymbolAddress((void**)&gT, g_T);
    cudaGetSymbolAddress((void**)&gM, g_M);

    cudaFuncSetAttribute(attn_kernel,
                         cudaFuncAttributeMaxDynamicSharedMemorySize, ATTN_SMEM);

    dim3 ggrid(DM / BN, MROWS / BM);      // (6, 32)

    // QKV projections
    gemm_bias_kernel<<<ggrid, 256>>>(x, Wq, bq, gQ, MROWS, DM, DM);
    gemm_bias_kernel<<<ggrid, 256>>>(x, Wk, bk, gK, MROWS, DM, DM);
    gemm_bias_kernel<<<ggrid, 256>>>(x, Wv, bv, gV, MROWS, DM, DM);

    // Fused (Q K^T) V per (b,h) slab
    dim3 agrid(SEQ / 64, BD * NH);        // (32, 24)
    attn_kernel<<<agrid, 256, ATTN_SMEM>>>(gQ, gK, gV, gT);

    // softmax over dk axis, writes "multi_head" buffer
    int sm_blocks = (FLATROWS * 32 + 255) / 256;
    softmax64_kernel<<<sm_blocks, 256>>>(gT, gM);

    // output projections (reuse gQ as intermediate)
    gemm_bias_kernel<<<ggrid, 256>>>(gM, Wo, bo, gQ, MROWS, DM, DM);
    gemm_bias_kernel<<<ggrid, 256>>>(gQ, Wf, bf, out, MROWS, DM, DM);
}

// round 3
// speedup vs baseline: 3.1198x; 3.1198x over previous
#include <cuda_runtime.h>
#include <cuda_bf16.h>

#define BD      2
#define SEQ     2048
#define DM      768
#define NH      12
#define DK      64
#define MROWS   (BD*SEQ)          // 4096
#define ATT_SCALE 0.125f
#define FLATROWS (BD*NH*SEQ)

typedef __nv_bfloat16 bf16;

// ===========================================================================
// mma.sync helpers (plain sm_103-legal: HMMA + ldmatrix)
// ===========================================================================
__device__ __forceinline__ unsigned smem_u32(const void* p) {
    unsigned a;
    asm("{ .reg .u64 t; cvta.to.shared.u64 t, %1; cvt.u32.u64 %0, t; }"
        : "=r"(a) : "l"(p));
    return a;
}
__device__ __forceinline__ void ldsm4(unsigned& r0, unsigned& r1, unsigned& r2,
                                      unsigned& r3, unsigned a) {
    asm volatile("ldmatrix.sync.aligned.m8n8.x4.shared.b16 {%0,%1,%2,%3}, [%4];"
        : "=r"(r0), "=r"(r1), "=r"(r2), "=r"(r3) : "r"(a));
}
__device__ __forceinline__ void ldsm4t(unsigned& r0, unsigned& r1, unsigned& r2,
                                       unsigned& r3, unsigned a) {
    asm volatile("ldmatrix.sync.aligned.m8n8.x4.trans.shared.b16 {%0,%1,%2,%3}, [%4];"
        : "=r"(r0), "=r"(r1), "=r"(r2), "=r"(r3) : "r"(a));
}
__device__ __forceinline__ void mma_bf16(float* c, const unsigned* a,
                                         unsigned b0, unsigned b1) {
    asm volatile("mma.sync.aligned.m16n8k16.row.col.f32.bf16.bf16.f32 "
        "{%0,%1,%2,%3},{%4,%5,%6,%7},{%8,%9},{%0,%1,%2,%3};"
        : "+f"(c[0]), "+f"(c[1]), "+f"(c[2]), "+f"(c[3])
        : "r"(a[0]), "r"(a[1]), "r"(a[2]), "r"(a[3]), "r"(b0), "r"(b1));
}
__device__ __forceinline__ unsigned pack_hilo(float x, float y, unsigned& lo) {
    bf16 hx = __float2bfloat16(x), hy = __float2bfloat16(y);
    bf16 lx = __float2bfloat16(x - __bfloat162float(hx));
    bf16 ly = __float2bfloat16(y - __bfloat162float(hy));
    lo = (unsigned)__bfloat16_as_ushort(lx) | ((unsigned)__bfloat16_as_ushort(ly) << 16);
    return (unsigned)__bfloat16_as_ushort(hx) | ((unsigned)__bfloat16_as_ushort(hy) << 16);
}

// ===========================================================================
// Scratch
// ===========================================================================
__device__ bf16 g_xhi[MROWS*DM], g_xlo[MROWS*DM];
__device__ bf16 g_Whi[5*DM*DM],  g_Wlo[5*DM*DM];
__device__ bf16 g_Qhi[MROWS*DM], g_Qlo[MROWS*DM];
__device__ bf16 g_Khi[MROWS*DM], g_Klo[MROWS*DM];
__device__ bf16 g_Vhi[MROWS*DM], g_Vlo[MROWS*DM];
__device__ bf16 g_Mhi[MROWS*DM], g_Mlo[MROWS*DM];
__device__ bf16 g_Hhi[MROWS*DM], g_Hlo[MROWS*DM];

// ===========================================================================
// fp32 -> bf16 hi/lo splitter
// ===========================================================================
__global__ void __launch_bounds__(256) cvt_hilo(
    const float* __restrict__ in, bf16* __restrict__ hi, bf16* __restrict__ lo, int n4)
{
    int i = blockIdx.x * blockDim.x + threadIdx.x;
    if (i >= n4) return;
    float4 v = reinterpret_cast<const float4*>(in)[i];
    uint2 hp, lp;
    hp.x = pack_hilo(v.x, v.y, lp.x);
    hp.y = pack_hilo(v.z, v.w, lp.y);
    reinterpret_cast<uint2*>(hi)[i] = hp;
    reinterpret_cast<uint2*>(lo)[i] = lp;
}

// ===========================================================================
// GEMM: C[4096,768] = A @ W^T + bias  (split-bf16, 3-pass)
// Tile 128x64, K-chunk 64. 256 threads = 8 warps (4 M x 2 N), warp 32x32.
// ===========================================================================
#define GLD 72                      // padded bf16 row (144B; ldmatrix conflict-free)
#define G_AH 0
#define G_AL (128*GLD)
#define G_BH (2*128*GLD)
#define G_BL (2*128*GLD + 64*GLD)
#define GEMM_SMEM ((2*128*GLD + 2*64*GLD) * 2)

__global__ void __launch_bounds__(256) mma_gemm(
    const bf16* __restrict__ Ahi, const bf16* __restrict__ Alo,
    const bf16* __restrict__ Bhi, const bf16* __restrict__ Blo,
    const float* __restrict__ bias,
    float* __restrict__ Cf, bf16* __restrict__ Chi, bf16* __restrict__ Clo)
{
    extern __shared__ bf16 sm[];
    const int tid = threadIdx.x, lane = tid & 31, wid = tid >> 5;
    const int wm = wid >> 1, wn = wid & 1;
    const int row0 = blockIdx.y * 128, col0 = blockIdx.x * 64;
    const unsigned sb = smem_u32(sm);

    float acc[2][4][4];
    #pragma unroll
    for (int i = 0; i < 2; i++)
        #pragma unroll
        for (int j = 0; j < 4; j++)
            #pragma unroll
            for (int k = 0; k < 4; k++) acc[i][j][k] = 0.0f;

    for (int kc = 0; kc < DM; kc += 64) {
        // load A hi/lo (128x64) and B hi/lo (64x64), 16B vectors
        #pragma unroll
        for (int u = 0; u < 4; u++) {
            int idx = u * 256 + tid;              // 1024 uint4 over both A tiles
            int r = idx >> 3, c = idx & 7;
            const uint4* s = reinterpret_cast<const uint4*>(
                (idx < 1024 ? Ahi : Ahi) + 0);    // placeholder, replaced below
            (void)s;
            uint4 vh = *reinterpret_cast<const uint4*>(Ahi + (size_t)(row0 + r) * DM + kc + c * 8);
            uint4 vl = *reinterpret_cast<const uint4*>(Alo + (size_t)(row0 + r) * DM + kc + c * 8);
            *reinterpret_cast<uint4*>(&sm[G_AH + r * GLD + c * 8]) = vh;
            *reinterpret_cast<uint4*>(&sm[G_AL + r * GLD + c * 8]) = vl;
        }
        #pragma unroll
        for (int u = 0; u < 2; u++) {
            int idx = u * 256 + tid;              // 512 uint4 per B tile
            int r = idx >> 3, c = idx & 7;
            uint4 vh = *reinterpret_cast<const uint4*>(Bhi + (size_t)(col0 + r) * DM + kc + c * 8);
            uint4 vl = *reinterpret_cast<const uint4*>(Blo + (size_t)(col0 + r) * DM + kc + c * 8);
            *reinterpret_cast<uint4*>(&sm[G_BH + r * GLD + c * 8]) = vh;
            *reinterpret_cast<uint4*>(&sm[G_BL + r * GLD + c * 8]) = vl;
        }
        __syncthreads();

        #pragma unroll
        for (int ks = 0; ks < 4; ks++) {
            const int kr = ks * 16;
            unsigned ah[2][4], al[2][4], bh[2][4], bl[2][4];
            #pragma unroll
            for (int mi = 0; mi < 2; mi++) {
                int m = wm * 32 + mi * 16 + (lane & 15);
                int kk = kr + (lane >> 4) * 8;
                ldsm4(ah[mi][0], ah[mi][1], ah[mi][2], ah[mi][3],
                      sb + (G_AH + m * GLD + kk) * 2);
                ldsm4(al[mi][0], al[mi][1], al[mi][2], al[mi][3],
                      sb + (G_AL + m * GLD + kk) * 2);
            }
            #pragma unroll
            for (int ni2 = 0; ni2 < 2; ni2++) {
                int n = wn * 32 + ni2 * 16 + (lane >> 4) * 8 + (lane & 7);
                int kk = kr + ((lane >> 3) & 1) * 8;
                ldsm4(bh[ni2][0], bh[ni2][1], bh[ni2][2], bh[ni2][3],
                      sb + (G_BH + n * GLD + kk) * 2);
                ldsm4(bl[ni2][0], bl[ni2][1], bl[ni2][2], bl[ni2][3],
                      sb + (G_BL + n * GLD + kk) * 2);
            }
            #pragma unroll
            for (int mi = 0; mi < 2; mi++)
                #pragma unroll
                for (int ni = 0; ni < 4; ni++) {
                    unsigned* bhp = &bh[ni >> 1][(ni & 1) * 2];
                    unsigned* blp = &bl[ni >> 1][(ni & 1) * 2];
                    mma_bf16(acc[mi][ni], ah[mi], bhp[0], bhp[1]);
                    mma_bf16(acc[mi][ni], ah[mi], blp[0], blp[1]);
                    mma_bf16(acc[mi][ni], al[mi], bhp[0], bhp[1]);
                }
        }
        __syncthreads();
    }

    // epilogue
    #pragma unroll
    for (int mi = 0; mi < 2; mi++)
        #pragma unroll
        for (int ni = 0; ni < 4; ni++) {
            int row = row0 + wm * 32 + mi * 16 + (lane >> 2);
            int col = col0 + wn * 32 + ni * 8 + (lane & 3) * 2;
            float2 bv = *reinterpret_cast<const float2*>(&bias[col]);
            #pragma unroll
            for (int h = 0; h < 2; h++) {
                int r = row + h * 8;
                float vx = acc[mi][ni][h * 2 + 0] + bv.x;
                float vy = acc[mi][ni][h * 2 + 1] + bv.y;
                size_t off = (size_t)r * DM + col;
                if (Cf) *reinterpret_cast<float2*>(&Cf[off]) = make_float2(vx, vy);
                if (Chi) {
                    unsigned lo, hi = pack_hilo(vx, vy, lo);
                    *reinterpret_cast<unsigned*>(&Chi[off]) = hi;
                    *reinterpret_cast<unsigned*>(&Clo[off]) = lo;
                }
            }
        }
}

// ===========================================================================
// Attention: per (head, 64-row s-tile): O = SCALE*(Q K^T) V, then softmax over
// dk=64 (block-local), emitting bf16 hi/lo. All matmuls split-bf16 3-pass mma.
// 128 threads = 4 warps (2x2 over 64x64).
// ===========================================================================
#define ALD 72
#define A_QH 0
#define A_QL (1*64*ALD)
#define A_KH (2*64*ALD)
#define A_KL (3*64*ALD)
#define A_VH (4*64*ALD)
#define A_VL (5*64*ALD)
#define A_SH (6*64*ALD)
#define A_SL (7*64*ALD)
#define A_OF (8*64*ALD)                 // float region starts here (bf16 units)
#define ATTN_SMEM (8*64*ALD*2 + 64*65*4)

__global__ void __launch_bounds__(128) attn_mma(
    const bf16* __restrict__ Qhi, const bf16* __restrict__ Qlo,
    const bf16* __restrict__ Khi, const bf16* __restrict__ Klo,
    const bf16* __restrict__ Vhi, const bf16* __restrict__ Vlo,
    bf16* __restrict__ Mhi, bf16* __restrict__ Mlo)
{
    extern __shared__ bf16 sm[];
    float* sO = reinterpret_cast<float*>(sm + A_OF);
    const int tid = threadIdx.x, lane = tid & 31, wid = tid >> 5;
    const int wm = wid >> 1, wn = wid & 1;
    const int bh = blockIdx.y;
    const int s0 = blockIdx.x * 64;
    const size_t base = (size_t)bh * SEQ * DK;
    const unsigned sb = smem_u32(sm);

    // load Q tiles once (64x64 each, 512 uint4, 128 threads -> 4 iters)
    #pragma unroll
    for (int u = 0; u < 4; u++) {
        int idx = u * 128 + tid;
        int r = idx >> 3, c = idx & 7;
        *reinterpret_cast<uint4*>(&sm[A_QH + r * ALD + c * 8]) =
            *reinterpret_cast<const uint4*>(Qhi + base + (size_t)(s0 + r) * DK + c * 8);
        *reinterpret_cast<uint4*>(&sm[A_QL + r * ALD + c * 8]) =
            *reinterpret_cast<const uint4*>(Qlo + base + (size_t)(s0 + r) * DK + c * 8);
    }

    float oacc[2][4][4];
    #pragma unroll
    for (int i = 0; i < 2; i++)
        #pragma unroll
        for (int j = 0; j < 4; j++)
            #pragma unroll
            for (int k = 0; k < 4; k++) oacc[i][j][k] = 0.0f;

    for (int t0 = 0; t0 < SEQ; t0 += 64) {
        // load K,V hi/lo tiles
        #pragma unroll
        for (int u = 0; u < 4; u++) {
            int idx = u * 128 + tid;
            int r = idx >> 3, c = idx & 7;
            size_t g = base + (size_t)(t0 + r) * DK + c * 8;
            *reinterpret_cast<uint4*>(&sm[A_KH + r * ALD + c * 8]) =
                *reinterpret_cast<const uint4*>(Khi + g);
            *reinterpret_cast<uint4*>(&sm[A_KL + r * ALD + c * 8]) =
                *reinterpret_cast<const uint4*>(Klo + g);
            *reinterpret_cast<uint4*>(&sm[A_VH + r * ALD + c * 8]) =
                *reinterpret_cast<const uint4*>(Vhi + g);
            *reinterpret_cast<uint4*>(&sm[A_VL + r * ALD + c * 8]) =
                *reinterpret_cast<const uint4*>(Vlo + g);
        }
        __syncthreads();

        // S = Q @ K^T  (64x64, k = d)
        float sacc[2][4][4];
        #pragma unroll
        for (int i = 0; i < 2; i++)
            #pragma unroll
            for (int j = 0; j < 4; j++)
                #pragma unroll
                for (int k = 0; k < 4; k++) sacc[i][j][k] = 0.0f;

        #pragma unroll
        for (int ks = 0; ks < 4; ks++) {
            const int kr = ks * 16;
            unsigned ah[2][4], al[2][4], bh_[2][4], bl_[2][4];
            #pragma unroll
            for (int mi = 0; mi < 2; mi++) {
                int m = wm * 32 + mi * 16 + (lane & 15);
                int kk = kr + (lane >> 4) * 8;
                ldsm4(ah[mi][0], ah[mi][1], ah[mi][2], ah[mi][3],
                      sb + (A_QH + m * ALD + kk) * 2);
                ldsm4(al[mi][0], al[mi][1], al[mi][2], al[mi][3],
                      sb + (A_QL + m * ALD + kk) * 2);
            }
            #pragma unroll
            for (int ni2 = 0; ni2 < 2; ni2++) {
                int n = wn * 32 + ni2 * 16 + (lane >> 4) * 8 + (lane & 7);
                int kk = kr + ((lane >> 3) & 1) * 8;
                ldsm4(bh_[ni2][0], bh_[ni2][1], bh_[ni2][2], bh_[ni2][3],
                      sb + (A_KH + n * ALD + kk) * 2);
                ldsm4(bl_[ni2][0], bl_[ni2][1], bl_[ni2][2], bl_[ni2][3],
                      sb + (A_KL + n * ALD + kk) * 2);
            }
            #pragma unroll
            for (int mi = 0; mi < 2; mi++)
                #pragma unroll
                for (int ni = 0; ni < 4; ni++) {
                    unsigned* bhp = &bh_[ni >> 1][(ni & 1) * 2];
                    unsigned* blp = &bl_[ni >> 1][(ni & 1) * 2];
                    mma_bf16(sacc[mi][ni], ah[mi], bhp[0], bhp[1]);
                    mma_bf16(sacc[mi][ni], ah[mi], blp[0], blp[1]);
                    mma_bf16(sacc[mi][ni], al[mi], bhp[0], bhp[1]);
                }
        }

        // convert S -> hi/lo smem
        #pragma unroll
        for (int mi = 0; mi < 2; mi++)
            #pragma unroll
            for (int ni = 0; ni < 4; ni++) {
                int row = wm * 32 + mi * 16 + (lane >> 2);
                int col = wn * 32 + ni * 8 + (lane & 3) * 2;
                #pragma unroll
                for (int h = 0; h < 2; h++) {
                    int r = row + h * 8;
                    unsigned lo, hi = pack_hilo(sacc[mi][ni][h*2], sacc[mi][ni][h*2+1], lo);
                    *reinterpret_cast<unsigned*>(&sm[A_SH + r * ALD + col]) = hi;
                    *reinterpret_cast<unsigned*>(&sm[A_SL + r * ALD + col]) = lo;
                }
            }
        __syncthreads();

        // O += S @ V  (k = t; V^T via trans ldmatrix)
        #pragma unroll
        for (int ks = 0; ks < 4; ks++) {
            const int kr = ks * 16;
            unsigned ah[2][4], al[2][4], bh_[2][4], bl_[2][4];
            #pragma unroll
            for (int mi = 0; mi < 2; mi++) {
                int m = wm * 32 + mi * 16 + (lane & 15);
                int kk = kr + (lane >> 4) * 8;
                ldsm4(ah[mi][0], ah[mi][1], ah[mi][2], ah[mi][3],
                      sb + (A_SH + m * ALD + kk) * 2);
                ldsm4(al[mi][0], al[mi][1], al[mi][2], al[mi][3],
                      sb + (A_SL + m * ALD + kk) * 2);
            }
            #pragma unroll
            for (int ni2 = 0; ni2 < 2; ni2++) {
                int n = wn * 32 + ni2 * 16 + (lane >> 4) * 8;
                int kk = kr + (lane & 7) + ((lane >> 3) & 1) * 8;
                ldsm4t(bh_[ni2][0], bh_[ni2][1], bh_[ni2][2], bh_[ni2][3],
                       sb + (A_VH + kk * ALD + n) * 2);
                ldsm4t(bl_[ni2][0], bl_[ni2][1], bl_[ni2][2], bl_[ni2][3],
                       sb + (A_VL + kk * ALD + n) * 2);
            }
            #pragma unroll
            for (int mi = 0; mi < 2; mi++)
                #pragma unroll
                for (int ni = 0; ni < 4; ni++) {
                    unsigned* bhp = &bh_[ni >> 1][(ni & 1) * 2];
                    unsigned* blp = &bl_[ni >> 1][(ni & 1) * 2];
                    mma_bf16(oacc[mi][ni], ah[mi], bhp[0], bhp[1]);
                    mma_bf16(oacc[mi][ni], ah[mi], blp[0], blp[1]);
                    mma_bf16(oacc[mi][ni], al[mi], bhp[0], bhp[1]);
                }
        }
        __syncthreads();
    }

    // write O*SCALE into fp32 smem
    #pragma unroll
    for (int mi = 0; mi < 2; mi++)
        #pragma unroll
        for (int ni = 0; ni < 4; ni++) {
            int row = wm * 32 + mi * 16 + (lane >> 2);
            int col = wn * 32 + ni * 8 + (lane & 3) * 2;
            #pragma unroll
            for (int h = 0; h < 2; h++) {
                int r = row + h * 8;
                sO[r * 65 + col]     = oacc[mi][ni][h*2]   * ATT_SCALE;
                sO[r * 65 + col + 1] = oacc[mi][ni][h*2+1] * ATT_SCALE;
            }
        }
    __syncthreads();

    // softmax over the 64 cols (dk axis), 16 rows per warp
    for (int i = 0; i < 16; i++) {
        int r = wid * 16 + i;
        float v0 = sO[r * 65 + lane], v1 = sO[r * 65 + lane + 32];
        float mx = fmaxf(v0, v1);
        #pragma unroll
        for (int o = 16; o > 0; o >>= 1)
            mx = fmaxf(mx, __shfl_xor_sync(0xffffffffu, mx, o));
        float e0 = __expf(v0 - mx), e1 = __expf(v1 - mx);
        float s = e0 + e1;
        #pragma unroll
        for (int o = 16; o > 0; o >>= 1) s += __shfl_xor_sync(0xffffffffu, s, o);
        float inv = 1.0f / s;
        float p0 = e0 * inv, p1 = e1 * inv;
        size_t g = base + (size_t)(s0 + r) * DK;
        bf16 h0 = __float2bfloat16(p0), h1 = __float2bfloat16(p1);
        Mhi[g + lane]      = h0;
        Mhi[g + lane + 32] = h1;
        Mlo[g + lane]      = __float2bfloat16(p0 - __bfloat162float(h0));
        Mlo[g + lane + 32] = __float2bfloat16(p1 - __bfloat162float(h1));
    }
}

// ===========================================================================
// Launch
// ===========================================================================
extern "C" void kernel_launch(void* const* d_in, const int* in_sizes, int n_in,
                              void* d_out, int out_size)
{
    const float* x  = (const float*)d_in[0];
    const float* Wq = (const float*)d_in[1];
    const float* bq = (const float*)d_in[2];
    const float* Wk = (const float*)d_in[3];
    const float* bk = (const float*)d_in[4];
    const float* Wv = (const float*)d_in[5];
    const float* bv = (const float*)d_in[6];
    const float* Wo = (const float*)d_in[7];
    const float* bo = (const float*)d_in[8];
    const float* Wf = (const float*)d_in[9];
    const float* bf_ = (const float*)d_in[10];
    float* out = (float*)d_out;

    bf16 *xhi, *xlo, *Whi, *Wlo, *Qhi, *Qlo, *Khi, *Klo, *Vhi, *Vlo, *Mhi, *Mlo, *Hhi, *Hlo;
    cudaGetSymbolAddress((void**)&xhi, g_xhi); cudaGetSymbolAddress((void**)&xlo, g_xlo);
    cudaGetSymbolAddress((void**)&Whi, g_Whi); cudaGetSymbolAddress((void**)&Wlo, g_Wlo);
    cudaGetSymbolAddress((void**)&Qhi, g_Qhi); cudaGetSymbolAddress((void**)&Qlo, g_Qlo);
    cudaGetSymbolAddress((void**)&Khi, g_Khi); cudaGetSymbolAddress((void**)&Klo, g_Klo);
    cudaGetSymbolAddress((void**)&Vhi, g_Vhi); cudaGetSymbolAddress((void**)&Vlo, g_Vlo);
    cudaGetSymbolAddress((void**)&Mhi, g_Mhi); cudaGetSymbolAddress((void**)&Mlo, g_Mlo);
    cudaGetSymbolAddress((void**)&Hhi, g_Hhi); cudaGetSymbolAddress((void**)&Hlo, g_Hlo);

    cudaFuncSetAttribute(mma_gemm, cudaFuncAttributeMaxDynamicSharedMemorySize, GEMM_SMEM);
    cudaFuncSetAttribute(attn_mma, cudaFuncAttributeMaxDynamicSharedMemorySize, ATTN_SMEM);

    const int WN = DM * DM;
    cvt_hilo<<<(MROWS*DM/4 + 255)/256, 256>>>(x, xhi, xlo, MROWS*DM/4);
    cvt_hilo<<<(WN/4 + 255)/256, 256>>>(Wq, Whi + 0*WN, Wlo + 0*WN, WN/4);
    cvt_hilo<<<(WN/4 + 255)/256, 256>>>(Wk, Whi + 1*WN, Wlo + 1*WN, WN/4);
    cvt_hilo<<<(WN/4 + 255)/256, 256>>>(Wv, Whi + 2*WN, Wlo + 2*WN, WN/4);
    cvt_hilo<<<(WN/4 + 255)/256, 256>>>(Wo, Whi + 3*WN, Wlo + 3*WN, WN/4);
    cvt_hilo<<<(WN/4 + 255)/256, 256>>>(Wf, Whi + 4*WN, Wlo + 4*WN, WN/4);

    dim3 ggrid(DM/64, MROWS/128);   // (12, 32)

    mma_gemm<<<ggrid, 256, GEMM_SMEM>>>(xhi, xlo, Whi+0*WN, Wlo+0*WN, bq, nullptr, Qhi, Qlo);
    mma_gemm<<<ggrid, 256, GEMM_SMEM>>>(xhi, xlo, Whi+1*WN, Wlo+1*WN, bk, nullptr, Khi, Klo);
    mma_gemm<<<ggrid, 256, GEMM_SMEM>>>(xhi, xlo, Whi+2*WN, Wlo+2*WN, bv, nullptr, Vhi, Vlo);

    dim3 agrid(SEQ/64, BD*NH);      // (32, 24)
    attn_mma<<<agrid, 128, ATTN_SMEM>>>(Qhi, Qlo, Khi, Klo, Vhi, Vlo, Mhi, Mlo);

    mma_gemm<<<ggrid, 256, GEMM_SMEM>>>(Mhi, Mlo, Whi+3*WN, Wlo+3*WN, bo, nullptr, Hhi, Hlo);
    mma_gemm<<<ggrid, 256, GEMM_SMEM>>>(Hhi, Hlo, Whi+4*WN, Wlo+4*WN, bf_, out, nullptr, nullptr);
}

// round 5
// speedup vs baseline: 3.4902x; 1.1187x over previous
#include <cuda_runtime.h>
#include <cuda_bf16.h>

#define BD      2
#define SEQ     2048
#define DM      768
#define NH      12
#define DK      64
#define MROWS   (BD*SEQ)
#define ATT_SCALE 0.125f

typedef __nv_bfloat16 bf16;

// ===========================================================================
// helpers
// ===========================================================================
__device__ __forceinline__ unsigned smem_u32(const void* p) {
    unsigned a;
    asm("{ .reg .u64 t; cvta.to.shared.u64 t, %1; cvt.u32.u64 %0, t; }"
        : "=r"(a) : "l"(p));
    return a;
}
__device__ __forceinline__ void ldsm4(unsigned& r0, unsigned& r1, unsigned& r2,
                                      unsigned& r3, unsigned a) {
    asm volatile("ldmatrix.sync.aligned.m8n8.x4.shared.b16 {%0,%1,%2,%3}, [%4];"
        : "=r"(r0), "=r"(r1), "=r"(r2), "=r"(r3) : "r"(a));
}
__device__ __forceinline__ void ldsm4t(unsigned& r0, unsigned& r1, unsigned& r2,
                                       unsigned& r3, unsigned a) {
    asm volatile("ldmatrix.sync.aligned.m8n8.x4.trans.shared.b16 {%0,%1,%2,%3}, [%4];"
        : "=r"(r0), "=r"(r1), "=r"(r2), "=r"(r3) : "r"(a));
}
__device__ __forceinline__ void mma_bf16(float* c, const unsigned* a,
                                         unsigned b0, unsigned b1) {
    asm volatile("mma.sync.aligned.m16n8k16.row.col.f32.bf16.bf16.f32 "
        "{%0,%1,%2,%3},{%4,%5,%6,%7},{%8,%9},{%0,%1,%2,%3};"
        : "+f"(c[0]), "+f"(c[1]), "+f"(c[2]), "+f"(c[3])
        : "r"(a[0]), "r"(a[1]), "r"(a[2]), "r"(a[3]), "r"(b0), "r"(b1));
}
__device__ __forceinline__ unsigned pack_hilo(float x, float y, unsigned& lo) {
    bf16 hx = __float2bfloat16(x), hy = __float2bfloat16(y);
    bf16 lx = __float2bfloat16(x - __bfloat162float(hx));
    bf16 ly = __float2bfloat16(y - __bfloat162float(hy));
    lo = (unsigned)__bfloat16_as_ushort(lx) | ((unsigned)__bfloat16_as_ushort(ly) << 16);
    return (unsigned)__bfloat16_as_ushort(hx) | ((unsigned)__bfloat16_as_ushort(hy) << 16);
}
#define CPA16(d, s) \
    asm volatile("cp.async.cg.shared.global [%0], [%1], 16;" :: "r"(d), "l"(s) : "memory")
#define CP_COMMIT() asm volatile("cp.async.commit_group;" ::: "memory")
#define CP_WAIT1()  asm volatile("cp.async.wait_group 1;" ::: "memory")
#define CP_WAIT0()  asm volatile("cp.async.wait_group 0;" ::: "memory")

// ===========================================================================
// scratch
// ===========================================================================
__device__ bf16 g_xhi[MROWS*DM], g_xlo[MROWS*DM];
__device__ bf16 g_Whi[5*DM*DM],  g_Wlo[5*DM*DM];
__device__ bf16 g_Qhi[MROWS*DM], g_Qlo[MROWS*DM];
__device__ bf16 g_Khi[MROWS*DM], g_Klo[MROWS*DM];
__device__ bf16 g_Vhi[MROWS*DM], g_Vlo[MROWS*DM];
__device__ bf16 g_Mhi[MROWS*DM], g_Mlo[MROWS*DM];
__device__ bf16 g_Hhi[MROWS*DM], g_Hlo[MROWS*DM];

// ===========================================================================
// fp32 -> bf16 hi/lo splitter
// ===========================================================================
__global__ void __launch_bounds__(256) cvt_hilo(
    const float* __restrict__ in, bf16* __restrict__ hi, bf16* __restrict__ lo, int n4)
{
    int i = blockIdx.x * blockDim.x + threadIdx.x;
    if (i >= n4) return;
    float4 v = reinterpret_cast<const float4*>(in)[i];
    uint2 hp, lp;
    hp.x = pack_hilo(v.x, v.y, lp.x);
    hp.y = pack_hilo(v.z, v.w, lp.y);
    reinterpret_cast<uint2*>(hi)[i] = hp;
    reinterpret_cast<uint2*>(lo)[i] = lp;
}

// ===========================================================================
// GEMM core: C[4096,768] = A @ W^T + bias (split-bf16 3-pass, cp.async 2-stage)
// Tile 128x64, 8 warps (4M x 2N), warp 32x32.
// ===========================================================================
#define GLD 72
#define G_AH_B 0
#define G_AL_B 18432
#define G_BH_B 36864
#define G_BL_B 46080
#define G_STAGE_B 55296
#define GEMM_SMEM (2*G_STAGE_B)

__device__ __forceinline__ void gemm_core(
    const bf16* __restrict__ Ahi, const bf16* __restrict__ Alo,
    const bf16* __restrict__ Bhi, const bf16* __restrict__ Blo,
    const float* __restrict__ bias,
    float* __restrict__ Cf, bf16* __restrict__ Chi, bf16* __restrict__ Clo)
{
    extern __shared__ char smc[];
    const int tid = threadIdx.x, lane = tid & 31, wid = tid >> 5;
    const int wm = wid >> 1, wn = wid & 1;
    const int row0 = blockIdx.y * 128, col0 = blockIdx.x * 64;
    const unsigned sb = smem_u32(smc);

    float acc[2][4][4];
    #pragma unroll
    for (int i = 0; i < 2; i++)
        #pragma unroll
        for (int j = 0; j < 4; j++)
            #pragma unroll
            for (int k = 0; k < 4; k++) acc[i][j][k] = 0.0f;

    auto issue = [&](int s, int kc) {
        unsigned stg = sb + s * G_STAGE_B;
        #pragma unroll
        for (int u = 0; u < 4; u++) {
            int idx = u * 256 + tid;
            int r = idx >> 3, c = idx & 7;
            const char* ga = (const char*)(Ahi + (size_t)(row0 + r) * DM + kc) + c * 16;
            const char* gl = (const char*)(Alo + (size_t)(row0 + r) * DM + kc) + c * 16;
            unsigned d = (unsigned)(r * GLD + c * 8) * 2;
            CPA16(stg + G_AH_B + d, ga);
            CPA16(stg + G_AL_B + d, gl);
        }
        #pragma unroll
        for (int u = 0; u < 2; u++) {
            int idx = u * 256 + tid;
            int r = idx >> 3, c = idx & 7;
            const char* gh = (const char*)(Bhi + (size_t)(col0 + r) * DM + kc) + c * 16;
            const char* gl = (const char*)(Blo + (size_t)(col0 + r) * DM + kc) + c * 16;
            unsigned d = (unsigned)(r * GLD + c * 8) * 2;
            CPA16(stg + G_BH_B + d, gh);
            CPA16(stg + G_BL_B + d, gl);
        }
    };

    issue(0, 0);
    CP_COMMIT();

    const int NC = DM / 64;   // 12
    for (int c = 0; c < NC; c++) {
        const int p = c & 1;
        if (c + 1 < NC) { issue(p ^ 1, (c + 1) * 64); CP_COMMIT(); CP_WAIT1(); }
        else            { CP_WAIT0(); }
        __syncthreads();

        const unsigned stg = sb + p * G_STAGE_B;
        #pragma unroll
        for (int ks = 0; ks < 4; ks++) {
            const int kr = ks * 16;
            unsigned ah[2][4], al[2][4], bh[2][4], bl[2][4];
            #pragma unroll
            for (int mi = 0; mi < 2; mi++) {
                int m = wm * 32 + mi * 16 + (lane & 15);
                int kk = kr + (lane >> 4) * 8;
                ldsm4(ah[mi][0], ah[mi][1], ah[mi][2], ah[mi][3],
                      stg + G_AH_B + (m * GLD + kk) * 2);
                ldsm4(al[mi][0], al[mi][1], al[mi][2], al[mi][3],
                      stg + G_AL_B + (m * GLD + kk) * 2);
            }
            #pragma unroll
            for (int ni2 = 0; ni2 < 2; ni2++) {
                int n = wn * 32 + ni2 * 16 + (lane >> 4) * 8 + (lane & 7);
                int kk = kr + ((lane >> 3) & 1) * 8;
                ldsm4(bh[ni2][0], bh[ni2][1], bh[ni2][2], bh[ni2][3],
                      stg + G_BH_B + (n * GLD + kk) * 2);
                ldsm4(bl[ni2][0], bl[ni2][1], bl[ni2][2], bl[ni2][3],
                      stg + G_BL_B + (n * GLD + kk) * 2);
            }
            #pragma unroll
            for (int mi = 0; mi < 2; mi++)
                #pragma unroll
                for (int ni = 0; ni < 4; ni++) {
                    unsigned* bhp = &bh[ni >> 1][(ni & 1) * 2];
                    unsigned* blp = &bl[ni >> 1][(ni & 1) * 2];
                    mma_bf16(acc[mi][ni], ah[mi], bhp[0], bhp[1]);
                    mma_bf16(acc[mi][ni], ah[mi], blp[0], blp[1]);
                    mma_bf16(acc[mi][ni], al[mi], bhp[0], bhp[1]);
                }
        }
        __syncthreads();
    }

    #pragma unroll
    for (int mi = 0; mi < 2; mi++)
        #pragma unroll
        for (int ni = 0; ni < 4; ni++) {
            int row = row0 + wm * 32 + mi * 16 + (lane >> 2);
            int col = col0 + wn * 32 + ni * 8 + (lane & 3) * 2;
            float2 bv = *reinterpret_cast<const float2*>(&bias[col]);
            #pragma unroll
            for (int h = 0; h < 2; h++) {
                int r = row + h * 8;
                float vx = acc[mi][ni][h * 2 + 0] + bv.x;
                float vy = acc[mi][ni][h * 2 + 1] + bv.y;
                size_t off = (size_t)r * DM + col;
                if (Cf) *reinterpret_cast<float2*>(&Cf[off]) = make_float2(vx, vy);
                if (Chi) {
                    unsigned lo, hi = pack_hilo(vx, vy, lo);
                    *reinterpret_cast<unsigned*>(&Chi[off]) = hi;
                    *reinterpret_cast<unsigned*>(&Clo[off]) = lo;
                }
            }
        }
}

__global__ void __launch_bounds__(256, 2) mma_gemm(
    const bf16* __restrict__ Ahi, const bf16* __restrict__ Alo,
    const bf16* __restrict__ Bhi, const bf16* __restrict__ Blo,
    const float* __restrict__ bias,
    float* __restrict__ Cf, bf16* __restrict__ Chi, bf16* __restrict__ Clo)
{
    gemm_core(Ahi, Alo, Bhi, Blo, bias, Cf, Chi, Clo);
}

__global__ void __launch_bounds__(256, 2) qkv_gemm(
    const bf16* __restrict__ xhi, const bf16* __restrict__ xlo,
    const bf16* __restrict__ Whi, const bf16* __restrict__ Wlo,
    const float* __restrict__ bq, const float* __restrict__ bk,
    const float* __restrict__ bv,
    bf16* __restrict__ Qhi, bf16* __restrict__ Qlo,
    bf16* __restrict__ Khi, bf16* __restrict__ Klo,
    bf16* __restrict__ Vhi, bf16* __restrict__ Vlo)
{
    const int z = blockIdx.z;
    const int WN = DM * DM;
    const float* bias = (z == 0) ? bq : (z == 1) ? bk : bv;
    bf16* Chi = (z == 0) ? Qhi : (z == 1) ? Khi : Vhi;
    bf16* Clo = (z == 0) ? Qlo : (z == 1) ? Klo : Vlo;
    gemm_core(xhi, xlo, Whi + (size_t)z * WN, Wlo + (size_t)z * WN, bias,
              nullptr, Chi, Clo);
}

// ===========================================================================
// Attention: 128 Q-rows per block, full t-loop, cp.async 2-stage K/V,
// fused softmax over dk=64 -> bf16 hi/lo. 8 warps, warp 32x32.
// ===========================================================================
#define ALD 72
#define A_QH_B 0
#define A_QL_B 18432
#define A_STG_B 36864                 // stage base (stage s: + s*36864)
#define A_KH_B 0
#define A_KL_B 9216
#define A_VH_B 18432
#define A_VL_B 27648
#define A_S_B  (A_STG_B + 2*36864)    // 110592: S hi base
#define A_SL_OFF 18432                // S lo = S hi + this
#define ATTN_SMEM (36864 + 2*36864 + 36864)   // Q + 2 stages + S = 147456

__global__ void __launch_bounds__(256, 1) attn_mma(
    const bf16* __restrict__ Qhi, const bf16* __restrict__ Qlo,
    const bf16* __restrict__ Khi, const bf16* __restrict__ Klo,
    const bf16* __restrict__ Vhi, const bf16* __restrict__ Vlo,
    bf16* __restrict__ Mhi, bf16* __restrict__ Mlo)
{
    extern __shared__ char sma[];
    const int tid = threadIdx.x, lane = tid & 31, wid = tid >> 5;
    const int wm = wid >> 1, wn = wid & 1;
    const int bh = blockIdx.y;
    const int s0 = blockIdx.x * 128;
    const size_t base = (size_t)bh * SEQ * DK;
    const unsigned sb = smem_u32(sma);
    const unsigned SH = sb + A_S_B;                // S hi (shared-window addr)
    const unsigned SL = SH + A_SL_OFF;             // S lo
    char* sSH = sma + A_S_B;                       // generic pointers, same region
    char* sSL = sSH + A_SL_OFF;
    float* sO = reinterpret_cast<float*>(sma + A_STG_B);     // overlay stage 0

    // load Q (128x64 hi/lo), plain vectorized
    #pragma unroll
    for (int u = 0; u < 4; u++) {
        int idx = u * 256 + tid;
        int r = idx >> 3, c = idx & 7;
        size_t g = base + (size_t)(s0 + r) * DK + c * 8;
        *reinterpret_cast<uint4*>(sma + A_QH_B + (r * ALD + c * 8) * 2) =
            *reinterpret_cast<const uint4*>(Qhi + g);
        *reinterpret_cast<uint4*>(sma + A_QL_B + (r * ALD + c * 8) * 2) =
            *reinterpret_cast<const uint4*>(Qlo + g);
    }

    auto issue = [&](int s, int t0) {
        unsigned stg = sb + A_STG_B + s * 36864;
        #pragma unroll
        for (int u = 0; u < 2; u++) {
            int idx = u * 256 + tid;
            int r = idx >> 3, c = idx & 7;
            size_t g = (base + (size_t)(t0 + r) * DK) * 2 + c * 16;  // byte offset
            unsigned d = (unsigned)(r * ALD + c * 8) * 2;
            CPA16(stg + A_KH_B + d, (const char*)Khi + g);
            CPA16(stg + A_KL_B + d, (const char*)Klo + g);
            CPA16(stg + A_VH_B + d, (const char*)Vhi + g);
            CPA16(stg + A_VL_B + d, (const char*)Vlo + g);
        }
    };

    float oacc[2][4][4];
    #pragma unroll
    for (int i = 0; i < 2; i++)
        #pragma unroll
        for (int j = 0; j < 4; j++)
            #pragma unroll
            for (int k = 0; k < 4; k++) oacc[i][j][k] = 0.0f;

    issue(0, 0);
    CP_COMMIT();

    const int NC = SEQ / 64;   // 32
    for (int c = 0; c < NC; c++) {
        const int p = c & 1;
        if (c + 1 < NC) { issue(p ^ 1, (c + 1) * 64); CP_COMMIT(); CP_WAIT1(); }
        else            { CP_WAIT0(); }
        __syncthreads();   // K/V(p) ready; also protects S vs prev O-compute

        const unsigned stg = sb + A_STG_B + p * 36864;

        // S = Q @ K^T
        float sacc[2][4][4];
        #pragma unroll
        for (int i = 0; i < 2; i++)
            #pragma unroll
            for (int j = 0; j < 4; j++)
                #pragma unroll
                for (int k = 0; k < 4; k++) sacc[i][j][k] = 0.0f;

        #pragma unroll
        for (int ks = 0; ks < 4; ks++) {
            const int kr = ks * 16;
            unsigned ah[2][4], al[2][4], bh_[2][4], bl_[2][4];
            #pragma unroll
            for (int mi = 0; mi < 2; mi++) {
                int m = wm * 32 + mi * 16 + (lane & 15);
                int kk = kr + (lane >> 4) * 8;
                ldsm4(ah[mi][0], ah[mi][1], ah[mi][2], ah[mi][3],
                      sb + A_QH_B + (m * ALD + kk) * 2);
                ldsm4(al[mi][0], al[mi][1], al[mi][2], al[mi][3],
                      sb + A_QL_B + (m * ALD + kk) * 2);
            }
            #pragma unroll
            for (int ni2 = 0; ni2 < 2; ni2++) {
                int n = wn * 32 + ni2 * 16 + (lane >> 4) * 8 + (lane & 7);
                int kk = kr + ((lane >> 3) & 1) * 8;
                ldsm4(bh_[ni2][0], bh_[ni2][1], bh_[ni2][2], bh_[ni2][3],
                      stg + A_KH_B + (n * ALD + kk) * 2);
                ldsm4(bl_[ni2][0], bl_[ni2][1], bl_[ni2][2], bl_[ni2][3],
                      stg + A_KL_B + (n * ALD + kk) * 2);
            }
            #pragma unroll
            for (int mi = 0; mi < 2; mi++)
                #pragma unroll
                for (int ni = 0; ni < 4; ni++) {
                    unsigned* bhp = &bh_[ni >> 1][(ni & 1) * 2];
                    unsigned* blp = &bl_[ni >> 1][(ni & 1) * 2];
                    mma_bf16(sacc[mi][ni], ah[mi], bhp[0], bhp[1]);
                    mma_bf16(sacc[mi][ni], ah[mi], blp[0], blp[1]);
                    mma_bf16(sacc[mi][ni], al[mi], bhp[0], bhp[1]);
                }
        }

        // S -> hi/lo smem
        #pragma unroll
        for (int mi = 0; mi < 2; mi++)
            #pragma unroll
            for (int ni = 0; ni < 4; ni++) {
                int row = wm * 32 + mi * 16 + (lane >> 2);
                int col = wn * 32 + ni * 8 + (lane & 3) * 2;
                #pragma unroll
                for (int h = 0; h < 2; h++) {
                    int r = row + h * 8;
                    unsigned lo, hi = pack_hilo(sacc[mi][ni][h*2], sacc[mi][ni][h*2+1], lo);
                    *reinterpret_cast<unsigned*>(sSH + (r * ALD + col) * 2) = hi;
                    *reinterpret_cast<unsigned*>(sSL + (r * ALD + col) * 2) = lo;
                }
            }
        __syncthreads();

        // O += S @ V
        #pragma unroll
        for (int ks = 0; ks < 4; ks++) {
            const int kr = ks * 16;
            unsigned ah[2][4], al[2][4], bh_[2][4], bl_[2][4];
            #pragma unroll
            for (int mi = 0; mi < 2; mi++) {
                int m = wm * 32 + mi * 16 + (lane & 15);
                int kk = kr + (lane >> 4) * 8;
                ldsm4(ah[mi][0], ah[mi][1], ah[mi][2], ah[mi][3],
                      SH + (m * ALD + kk) * 2);
                ldsm4(al[mi][0], al[mi][1], al[mi][2], al[mi][3],
                      SL + (m * ALD + kk) * 2);
            }
            #pragma unroll
            for (int ni2 = 0; ni2 < 2; ni2++) {
                int n = wn * 32 + ni2 * 16 + (lane >> 4) * 8;
                int kk = kr + (lane & 7) + ((lane >> 3) & 1) * 8;
                ldsm4t(bh_[ni2][0], bh_[ni2][1], bh_[ni2][2], bh_[ni2][3],
                       stg + A_VH_B + (kk * ALD + n) * 2);
                ldsm4t(bl_[ni2][0], bl_[ni2][1], bl_[ni2][2], bl_[ni2][3],
                       stg + A_VL_B + (kk * ALD + n) * 2);
            }
            #pragma unroll
            for (int mi = 0; mi < 2; mi++)
                #pragma unroll
                for (int ni = 0; ni < 4; ni++) {
                    unsigned* bhp = &bh_[ni >> 1][(ni & 1) * 2];
                    unsigned* blp = &bl_[ni >> 1][(ni & 1) * 2];
                    mma_bf16(oacc[mi][ni], ah[mi], bhp[0], bhp[1]);
                    mma_bf16(oacc[mi][ni], ah[mi], blp[0], blp[1]);
                    mma_bf16(oacc[mi][ni], al[mi], bhp[0], bhp[1]);
                }
        }
        __syncthreads();   // done reading stage p & S before next overwrite
    }

    // O*SCALE -> fp32 smem (overlay on stage 0)
    #pragma unroll
    for (int mi = 0; mi < 2; mi++)
        #pragma unroll
        for (int ni = 0; ni < 4; ni++) {
            int row = wm * 32 + mi * 16 + (lane >> 2);
            int col = wn * 32 + ni * 8 + (lane & 3) * 2;
            #pragma unroll
            for (int h = 0; h < 2; h++) {
                int r = row + h * 8;
                sO[r * 65 + col]     = oacc[mi][ni][h*2]   * ATT_SCALE;
                sO[r * 65 + col + 1] = oacc[mi][ni][h*2+1] * ATT_SCALE;
            }
        }
    __syncthreads();

    // softmax over dk=64, 16 rows per warp
    #pragma unroll
    for (int i = 0; i < 16; i++) {
        int r = wid * 16 + i;
        float v0 = sO[r * 65 + lane], v1 = sO[r * 65 + lane + 32];
        float mx = fmaxf(v0, v1);
        #pragma unroll
        for (int o = 16; o > 0; o >>= 1)
            mx = fmaxf(mx, __shfl_xor_sync(0xffffffffu, mx, o));
        float e0 = __expf(v0 - mx), e1 = __expf(v1 - mx);
        float s = e0 + e1;
        #pragma unroll
        for (int o = 16; o > 0; o >>= 1) s += __shfl_xor_sync(0xffffffffu, s, o);
        float inv = 1.0f / s;
        float p0 = e0 * inv, p1 = e1 * inv;
        size_t g = base + (size_t)(s0 + r) * DK;
        bf16 h0 = __float2bfloat16(p0), h1 = __float2bfloat16(p1);
        Mhi[g + lane]      = h0;
        Mhi[g + lane + 32] = h1;
        Mlo[g + lane]      = __float2bfloat16(p0 - __bfloat162float(h0));
        Mlo[g + lane + 32] = __float2bfloat16(p1 - __bfloat162float(h1));
    }
}

// ===========================================================================
// Launch
// ===========================================================================
extern "C" void kernel_launch(void* const* d_in, const int* in_sizes, int n_in,
                              void* d_out, int out_size)
{
    const float* x  = (const float*)d_in[0];
    const float* Wq = (const float*)d_in[1];
    const float* bq = (const float*)d_in[2];
    const float* Wk = (const float*)d_in[3];
    const float* bk = (const float*)d_in[4];
    const float* Wv = (const float*)d_in[5];
    const float* bv = (const float*)d_in[6];
    const float* Wo = (const float*)d_in[7];
    const float* bo = (const float*)d_in[8];
    const float* Wf = (const float*)d_in[9];
    const float* bf_ = (const float*)d_in[10];
    float* out = (float*)d_out;

    bf16 *xhi, *xlo, *Whi, *Wlo, *Qhi, *Qlo, *Khi, *Klo, *Vhi, *Vlo, *Mhi, *Mlo, *Hhi, *Hlo;
    cudaGetSymbolAddress((void**)&xhi, g_xhi); cudaGetSymbolAddress((void**)&xlo, g_xlo);
    cudaGetSymbolAddress((void**)&Whi, g_Whi); cudaGetSymbolAddress((void**)&Wlo, g_Wlo);
    cudaGetSymbolAddress((void**)&Qhi, g_Qhi); cudaGetSymbolAddress((void**)&Qlo, g_Qlo);
    cudaGetSymbolAddress((void**)&Khi, g_Khi); cudaGetSymbolAddress((void**)&Klo, g_Klo);
    cudaGetSymbolAddress((void**)&Vhi, g_Vhi); cudaGetSymbolAddress((void**)&Vlo, g_Vlo);
    cudaGetSymbolAddress((void**)&Mhi, g_Mhi); cudaGetSymbolAddress((void**)&Mlo, g_Mlo);
    cudaGetSymbolAddress((void**)&Hhi, g_Hhi); cudaGetSymbolAddress((void**)&Hlo, g_Hlo);

    cudaFuncSetAttribute(mma_gemm, cudaFuncAttributeMaxDynamicSharedMemorySize, GEMM_SMEM);
    cudaFuncSetAttribute(qkv_gemm, cudaFuncAttributeMaxDynamicSharedMemorySize, GEMM_SMEM);
    cudaFuncSetAttribute(attn_mma, cudaFuncAttributeMaxDynamicSharedMemorySize, ATTN_SMEM);

    const int WN = DM * DM;
    cvt_hilo<<<(MROWS*DM/4 + 255)/256, 256>>>(x, xhi, xlo, MROWS*DM/4);
    cvt_hilo<<<(WN/4 + 255)/256, 256>>>(Wq, Whi + 0*WN, Wlo + 0*WN, WN/4);
    cvt_hilo<<<(WN/4 + 255)/256, 256>>>(Wk, Whi + 1*WN, Wlo + 1*WN, WN/4);
    cvt_hilo<<<(WN/4 + 255)/256, 256>>>(Wv, Whi + 2*WN, Wlo + 2*WN, WN/4);
    cvt_hilo<<<(WN/4 + 255)/256, 256>>>(Wo, Whi + 3*WN, Wlo + 3*WN, WN/4);
    cvt_hilo<<<(WN/4 + 255)/256, 256>>>(Wf, Whi + 4*WN, Wlo + 4*WN, WN/4);

    dim3 qgrid(DM/64, MROWS/128, 3);   // (12, 32, 3)
    qkv_gemm<<<qgrid, 256, GEMM_SMEM>>>(xhi, xlo, Whi, Wlo, bq, bk, bv,
                                        Qhi, Qlo, Khi, Klo, Vhi, Vlo);

    dim3 agrid(SEQ/128, BD*NH);        // (16, 24)
    attn_mma<<<agrid, 256, ATTN_SMEM>>>(Qhi, Qlo, Khi, Klo, Vhi, Vlo, Mhi, Mlo);

    dim3 ggrid(DM/64, MROWS/128);      // (12, 32)
    mma_gemm<<<ggrid, 256, GEMM_SMEM>>>(Mhi, Mlo, Whi+3*(size_t)WN, Wlo+3*(size_t)WN, bo, nullptr, Hhi, Hlo);
    mma_gemm<<<ggrid, 256, GEMM_SMEM>>>(Hhi, Hlo, Whi+4*(size_t)WN, Wlo+4*(size_t)WN, bf_, out, nullptr, nullptr);
}

// round 6
// speedup vs baseline: 3.8861x; 1.1134x over previous
#include <cuda_runtime.h>
#include <cuda_bf16.h>

#define BD      2
#define SEQ     2048
#define DM      768
#define NH      12
#define DK      64
#define MROWS   (BD*SEQ)
#define ATT_SCALE 0.125f

typedef __nv_bfloat16 bf16;

// ===========================================================================
// helpers
// ===========================================================================
__device__ __forceinline__ unsigned smem_u32(const void* p) {
    unsigned a;
    asm("{ .reg .u64 t; cvta.to.shared.u64 t, %1; cvt.u32.u64 %0, t; }"
        : "=r"(a) : "l"(p));
    return a;
}
__device__ __forceinline__ void ldsm4(unsigned& r0, unsigned& r1, unsigned& r2,
                                      unsigned& r3, unsigned a) {
    asm volatile("ldmatrix.sync.aligned.m8n8.x4.shared.b16 {%0,%1,%2,%3}, [%4];"
        : "=r"(r0), "=r"(r1), "=r"(r2), "=r"(r3) : "r"(a));
}
__device__ __forceinline__ void ldsm4t(unsigned& r0, unsigned& r1, unsigned& r2,
                                       unsigned& r3, unsigned a) {
    asm volatile("ldmatrix.sync.aligned.m8n8.x4.trans.shared.b16 {%0,%1,%2,%3}, [%4];"
        : "=r"(r0), "=r"(r1), "=r"(r2), "=r"(r3) : "r"(a));
}
__device__ __forceinline__ void mma_bf16(float* c, const unsigned* a,
                                         unsigned b0, unsigned b1) {
    asm volatile("mma.sync.aligned.m16n8k16.row.col.f32.bf16.bf16.f32 "
        "{%0,%1,%2,%3},{%4,%5,%6,%7},{%8,%9},{%0,%1,%2,%3};"
        : "+f"(c[0]), "+f"(c[1]), "+f"(c[2]), "+f"(c[3])
        : "r"(a[0]), "r"(a[1]), "r"(a[2]), "r"(a[3]), "r"(b0), "r"(b1));
}
__device__ __forceinline__ unsigned pack_hilo(float x, float y, unsigned& lo) {
    bf16 hx = __float2bfloat16(x), hy = __float2bfloat16(y);
    bf16 lx = __float2bfloat16(x - __bfloat162float(hx));
    bf16 ly = __float2bfloat16(y - __bfloat162float(hy));
    lo = (unsigned)__bfloat16_as_ushort(lx) | ((unsigned)__bfloat16_as_ushort(ly) << 16);
    return (unsigned)__bfloat16_as_ushort(hx) | ((unsigned)__bfloat16_as_ushort(hy) << 16);
}
#define CPA16(d, s) \
    asm volatile("cp.async.cg.shared.global [%0], [%1], 16;" :: "r"(d), "l"(s) : "memory")
#define CP_COMMIT() asm volatile("cp.async.commit_group;" ::: "memory")
#define CP_WAIT0()  asm volatile("cp.async.wait_group 0;" ::: "memory")

// ===========================================================================
// scratch
// ===========================================================================
__device__ bf16 g_xhi[MROWS*DM], g_xlo[MROWS*DM];
__device__ bf16 g_Whi[5*DM*DM],  g_Wlo[5*DM*DM];
__device__ bf16 g_Qhi[MROWS*DM], g_Qlo[MROWS*DM];
__device__ bf16 g_Khi[MROWS*DM], g_Klo[MROWS*DM];
__device__ bf16 g_Vhi[MROWS*DM], g_Vlo[MROWS*DM];
__device__ bf16 g_Mhi[MROWS*DM], g_Mlo[MROWS*DM];
__device__ bf16 g_Hhi[MROWS*DM], g_Hlo[MROWS*DM];

// ===========================================================================
// merged fp32 -> bf16 hi/lo splitter: x + all 5 weights in ONE launch
// ===========================================================================
#define N4X (MROWS*DM/4)
#define N4W (DM*DM/4)
__global__ void __launch_bounds__(256) cvt_all(
    const float* __restrict__ x,
    const float* __restrict__ Wq, const float* __restrict__ Wk,
    const float* __restrict__ Wv, const float* __restrict__ Wo,
    const float* __restrict__ Wf,
    bf16* __restrict__ xhi, bf16* __restrict__ xlo,
    bf16* __restrict__ Whi, bf16* __restrict__ Wlo)
{
    int i = blockIdx.x * blockDim.x + threadIdx.x;
    const float* src; bf16 *hi, *lo; int off;
    if (i < N4X) { src = x; hi = xhi; lo = xlo; off = i; }
    else {
        int j = i - N4X;
        if (j >= 5 * N4W) return;
        int w = j / N4W;
        off = j - w * N4W;
        src = (w == 0) ? Wq : (w == 1) ? Wk : (w == 2) ? Wv : (w == 3) ? Wo : Wf;
        hi = Whi + (size_t)w * (DM*DM);
        lo = Wlo + (size_t)w * (DM*DM);
    }
    float4 v = reinterpret_cast<const float4*>(src)[off];
    uint2 hp, lp;
    hp.x = pack_hilo(v.x, v.y, lp.x);
    hp.y = pack_hilo(v.z, v.w, lp.y);
    reinterpret_cast<uint2*>(hi)[off] = hp;
    reinterpret_cast<uint2*>(lo)[off] = lp;
}

// ===========================================================================
// GEMM core: C[4096,768] = A @ W^T + bias (split-bf16 3-pass, cp.async 2-stage)
// Tile 128x64, 8 warps (4M x 2N), warp 32x32. One barrier per K-chunk.
// ===========================================================================
#define GLD 72
#define G_AH_B 0
#define G_AL_B 18432
#define G_BH_B 36864
#define G_BL_B 46080
#define G_STAGE_B 55296
#define GEMM_SMEM (2*G_STAGE_B)

__device__ __forceinline__ void gemm_core(
    const bf16* __restrict__ Ahi, const bf16* __restrict__ Alo,
    const bf16* __restrict__ Bhi, const bf16* __restrict__ Blo,
    const float* __restrict__ bias,
    float* __restrict__ Cf, bf16* __restrict__ Chi, bf16* __restrict__ Clo)
{
    extern __shared__ char smc[];
    const int tid = threadIdx.x, lane = tid & 31, wid = tid >> 5;
    const int wm = wid >> 1, wn = wid & 1;
    const int row0 = blockIdx.y * 128, col0 = blockIdx.x * 64;
    const unsigned sb = smem_u32(smc);

    float acc[2][4][4];
    #pragma unroll
    for (int i = 0; i < 2; i++)
        #pragma unroll
        for (int j = 0; j < 4; j++)
            #pragma unroll
            for (int k = 0; k < 4; k++) acc[i][j][k] = 0.0f;

    auto issue = [&](int s, int kc) {
        unsigned stg = sb + s * G_STAGE_B;
        #pragma unroll
        for (int u = 0; u < 4; u++) {
            int idx = u * 256 + tid;
            int r = idx >> 3, c = idx & 7;
            const char* ga = (const char*)(Ahi + (size_t)(row0 + r) * DM + kc) + c * 16;
            const char* gl = (const char*)(Alo + (size_t)(row0 + r) * DM + kc) + c * 16;
            unsigned d = (unsigned)(r * GLD + c * 8) * 2;
            CPA16(stg + G_AH_B + d, ga);
            CPA16(stg + G_AL_B + d, gl);
        }
        #pragma unroll
        for (int u = 0; u < 2; u++) {
            int idx = u * 256 + tid;
            int r = idx >> 3, c = idx & 7;
            const char* gh = (const char*)(Bhi + (size_t)(col0 + r) * DM + kc) + c * 16;
            const char* gl = (const char*)(Blo + (size_t)(col0 + r) * DM + kc) + c * 16;
            unsigned d = (unsigned)(r * GLD + c * 8) * 2;
            CPA16(stg + G_BH_B + d, gh);
            CPA16(stg + G_BL_B + d, gl);
        }
    };

    issue(0, 0);
    CP_COMMIT();

    const int NC = DM / 64;   // 12
    for (int c = 0; c < NC; c++) {
        const int p = c & 1;
        CP_WAIT0();
        __syncthreads();
        if (c + 1 < NC) { issue(p ^ 1, (c + 1) * 64); CP_COMMIT(); }

        const unsigned stg = sb + p * G_STAGE_B;
        #pragma unroll
        for (int ks = 0; ks < 4; ks++) {
            const int kr = ks * 16;
            unsigned ah[2][4], al[2][4], bh[2][4], bl[2][4];
            #pragma unroll
            for (int mi = 0; mi < 2; mi++) {
                int m = wm * 32 + mi * 16 + (lane & 15);
                int kk = kr + (lane >> 4) * 8;
                ldsm4(ah[mi][0], ah[mi][1], ah[mi][2], ah[mi][3],
                      stg + G_AH_B + (m * GLD + kk) * 2);
                ldsm4(al[mi][0], al[mi][1], al[mi][2], al[mi][3],
                      stg + G_AL_B + (m * GLD + kk) * 2);
            }
            #pragma unroll
            for (int ni2 = 0; ni2 < 2; ni2++) {
                int n = wn * 32 + ni2 * 16 + (lane >> 4) * 8 + (lane & 7);
                int kk = kr + ((lane >> 3) & 1) * 8;
                ldsm4(bh[ni2][0], bh[ni2][1], bh[ni2][2], bh[ni2][3],
                      stg + G_BH_B + (n * GLD + kk) * 2);
                ldsm4(bl[ni2][0], bl[ni2][1], bl[ni2][2], bl[ni2][3],
                      stg + G_BL_B + (n * GLD + kk) * 2);
            }
            #pragma unroll
            for (int mi = 0; mi < 2; mi++)
                #pragma unroll
                for (int ni = 0; ni < 4; ni++) {
                    unsigned* bhp = &bh[ni >> 1][(ni & 1) * 2];
                    unsigned* blp = &bl[ni >> 1][(ni & 1) * 2];
                    mma_bf16(acc[mi][ni], ah[mi], bhp[0], bhp[1]);
                    mma_bf16(acc[mi][ni], ah[mi], blp[0], blp[1]);
                    mma_bf16(acc[mi][ni], al[mi], bhp[0], bhp[1]);
                }
        }
    }

    #pragma unroll
    for (int mi = 0; mi < 2; mi++)
        #pragma unroll
        for (int ni = 0; ni < 4; ni++) {
            int row = row0 + wm * 32 + mi * 16 + (lane >> 2);
            int col = col0 + wn * 32 + ni * 8 + (lane & 3) * 2;
            float2 bv = *reinterpret_cast<const float2*>(&bias[col]);
            #pragma unroll
            for (int h = 0; h < 2; h++) {
                int r = row + h * 8;
                float vx = acc[mi][ni][h * 2 + 0] + bv.x;
                float vy = acc[mi][ni][h * 2 + 1] + bv.y;
                size_t off = (size_t)r * DM + col;
                if (Cf) *reinterpret_cast<float2*>(&Cf[off]) = make_float2(vx, vy);
                if (Chi) {
                    unsigned lo, hi = pack_hilo(vx, vy, lo);
                    *reinterpret_cast<unsigned*>(&Chi[off]) = hi;
                    *reinterpret_cast<unsigned*>(&Clo[off]) = lo;
                }
            }
        }
}

__global__ void __launch_bounds__(256, 2) mma_gemm(
    const bf16* __restrict__ Ahi, const bf16* __restrict__ Alo,
    const bf16* __restrict__ Bhi, const bf16* __restrict__ Blo,
    const float* __restrict__ bias,
    float* __restrict__ Cf, bf16* __restrict__ Chi, bf16* __restrict__ Clo)
{
    gemm_core(Ahi, Alo, Bhi, Blo, bias, Cf, Chi, Clo);
}

__global__ void __launch_bounds__(256, 2) qkv_gemm(
    const bf16* __restrict__ xhi, const bf16* __restrict__ xlo,
    const bf16* __restrict__ Whi, const bf16* __restrict__ Wlo,
    const float* __restrict__ bq, const float* __restrict__ bk,
    const float* __restrict__ bv,
    bf16* __restrict__ Qhi, bf16* __restrict__ Qlo,
    bf16* __restrict__ Khi, bf16* __restrict__ Klo,
    bf16* __restrict__ Vhi, bf16* __restrict__ Vlo)
{
    const int z = blockIdx.z;
    const int WN = DM * DM;
    const float* bias = (z == 0) ? bq : (z == 1) ? bk : bv;
    bf16* Chi = (z == 0) ? Qhi : (z == 1) ? Khi : Vhi;
    bf16* Clo = (z == 0) ? Qlo : (z == 1) ? Klo : Vlo;
    gemm_core(xhi, xlo, Whi + (size_t)z * WN, Wlo + (size_t)z * WN, bias,
              nullptr, Chi, Clo);
}

// ===========================================================================
// Attention: 128 Q-rows/block, 8 warps. S stays in registers (acc fragment ==
// A fragment); warps split the t-range; one cross-warp O reduction at the end.
// ===========================================================================
#define ALD 72
#define A_QH_B 0
#define A_QL_B 18432
#define A_STG_B 36864
#define A_KH_B 0
#define A_KL_B 9216
#define A_VH_B 18432
#define A_VL_B 27648
#define ATTN_SMEM (36864 + 2*36864)   // 110592
#define OLD 66

__global__ void __launch_bounds__(256) attn_mma(
    const bf16* __restrict__ Qhi, const bf16* __restrict__ Qlo,
    const bf16* __restrict__ Khi, const bf16* __restrict__ Klo,
    const bf16* __restrict__ Vhi, const bf16* __restrict__ Vlo,
    bf16* __restrict__ Mhi, bf16* __restrict__ Mlo)
{
    extern __shared__ char sma[];
    const int tid = threadIdx.x, lane = tid & 31, wid = tid >> 5;
    const int wm = wid >> 1, wn = wid & 1;
    const int bh = blockIdx.y;
    const int s0 = blockIdx.x * 128;
    const size_t base = (size_t)bh * SEQ * DK;
    const unsigned sb = smem_u32(sma);

    // load Q (128x64 hi/lo)
    #pragma unroll
    for (int u = 0; u < 4; u++) {
        int idx = u * 256 + tid;
        int r = idx >> 3, c = idx & 7;
        size_t g = base + (size_t)(s0 + r) * DK + c * 8;
        *reinterpret_cast<uint4*>(sma + A_QH_B + (r * ALD + c * 8) * 2) =
            *reinterpret_cast<const uint4*>(Qhi + g);
        *reinterpret_cast<uint4*>(sma + A_QL_B + (r * ALD + c * 8) * 2) =
            *reinterpret_cast<const uint4*>(Qlo + g);
    }

    auto issue = [&](int s, int t0) {
        unsigned stg = sb + A_STG_B + s * 36864;
        #pragma unroll
        for (int u = 0; u < 2; u++) {
            int idx = u * 256 + tid;
            int r = idx >> 3, c = idx & 7;
            size_t g = (base + (size_t)(t0 + r) * DK) * 2 + c * 16;
            unsigned d = (unsigned)(r * ALD + c * 8) * 2;
            CPA16(stg + A_KH_B + d, (const char*)Khi + g);
            CPA16(stg + A_KL_B + d, (const char*)Klo + g);
            CPA16(stg + A_VH_B + d, (const char*)Vhi + g);
            CPA16(stg + A_VL_B + d, (const char*)Vlo + g);
        }
    };

    float oacc[2][8][4];
    #pragma unroll
    for (int i = 0; i < 2; i++)
        #pragma unroll
        for (int j = 0; j < 8; j++)
            #pragma unroll
            for (int k = 0; k < 4; k++) oacc[i][j][k] = 0.0f;

    issue(0, 0);
    CP_COMMIT();

    const int NC = SEQ / 64;   // 32
    for (int c = 0; c < NC; c++) {
        const int p = c & 1;
        CP_WAIT0();
        __syncthreads();
        if (c + 1 < NC) { issue(p ^ 1, (c + 1) * 64); CP_COMMIT(); }

        const unsigned stg = sb + A_STG_B + p * 36864;

        // S = Q @ K^T (rows wm*32..+32, t-cols wn*32..+32)
        float sacc[2][4][4];
        #pragma unroll
        for (int i = 0; i < 2; i++)
            #pragma unroll
            for (int j = 0; j < 4; j++)
                #pragma unroll
                for (int k = 0; k < 4; k++) sacc[i][j][k] = 0.0f;

        #pragma unroll
        for (int ks = 0; ks < 4; ks++) {
            const int kr = ks * 16;
            unsigned ah[2][4], al[2][4], bh_[2][4], bl_[2][4];
            #pragma unroll
            for (int mi = 0; mi < 2; mi++) {
                int m = wm * 32 + mi * 16 + (lane & 15);
                int kk = kr + (lane >> 4) * 8;
                ldsm4(ah[mi][0], ah[mi][1], ah[mi][2], ah[mi][3],
                      sb + A_QH_B + (m * ALD + kk) * 2);
                ldsm4(al[mi][0], al[mi][1], al[mi][2], al[mi][3],
                      sb + A_QL_B + (m * ALD + kk) * 2);
            }
            #pragma unroll
            for (int ni2 = 0; ni2 < 2; ni2++) {
                int n = wn * 32 + ni2 * 16 + (lane >> 4) * 8 + (lane & 7);
                int kk = kr + ((lane >> 3) & 1) * 8;
                ldsm4(bh_[ni2][0], bh_[ni2][1], bh_[ni2][2], bh_[ni2][3],
                      stg + A_KH_B + (n * ALD + kk) * 2);
                ldsm4(bl_[ni2][0], bl_[ni2][1], bl_[ni2][2], bl_[ni2][3],
                      stg + A_KL_B + (n * ALD + kk) * 2);
            }
            #pragma unroll
            for (int mi = 0; mi < 2; mi++)
                #pragma unroll
                for (int ni = 0; ni < 4; ni++) {
                    unsigned* bhp = &bh_[ni >> 1][(ni & 1) * 2];
                    unsigned* blp = &bl_[ni >> 1][(ni & 1) * 2];
                    mma_bf16(sacc[mi][ni], ah[mi], bhp[0], bhp[1]);
                    mma_bf16(sacc[mi][ni], ah[mi], blp[0], blp[1]);
                    mma_bf16(sacc[mi][ni], al[mi], bhp[0], bhp[1]);
                }
        }

        // O += (S*SCALE) @ V with S as register A-fragments
        #pragma unroll
        for (int j = 0; j < 2; j++) {
            unsigned sa_h[2][4], sa_l[2][4];
            #pragma unroll
            for (int mi = 0; mi < 2; mi++) {
                float* t0 = sacc[mi][2*j];
                float* t1 = sacc[mi][2*j + 1];
                sa_h[mi][0] = pack_hilo(t0[0]*ATT_SCALE, t0[1]*ATT_SCALE, sa_l[mi][0]);
                sa_h[mi][1] = pack_hilo(t0[2]*ATT_SCALE, t0[3]*ATT_SCALE, sa_l[mi][1]);
                sa_h[mi][2] = pack_hilo(t1[0]*ATT_SCALE, t1[1]*ATT_SCALE, sa_l[mi][2]);
                sa_h[mi][3] = pack_hilo(t1[2]*ATT_SCALE, t1[3]*ATT_SCALE, sa_l[mi][3]);
            }
            int kk = wn * 32 + j * 16 + (lane & 7) + ((lane >> 3) & 1) * 8;
            unsigned vh[4][4], vl[4][4];
            #pragma unroll
            for (int no2 = 0; no2 < 4; no2++) {
                int n = no2 * 16 + (lane >> 4) * 8;
                ldsm4t(vh[no2][0], vh[no2][1], vh[no2][2], vh[no2][3],
                       stg + A_VH_B + (kk * ALD + n) * 2);
                ldsm4t(vl[no2][0], vl[no2][1], vl[no2][2], vl[no2][3],
                       stg + A_VL_B + (kk * ALD + n) * 2);
            }
            #pragma unroll
            for (int mi = 0; mi < 2; mi++)
                #pragma unroll
                for (int no = 0; no < 8; no++) {
                    unsigned* bhp = &vh[no >> 1][(no & 1) * 2];
                    unsigned* blp = &vl[no >> 1][(no & 1) * 2];
                    mma_bf16(oacc[mi][no], sa_h[mi], bhp[0], bhp[1]);
                    mma_bf16(oacc[mi][no], sa_h[mi], blp[0], blp[1]);
                    mma_bf16(oacc[mi][no], sa_l[mi], bhp[0], bhp[1]);
                }
        }
    }

    // cross-warp O reduction
    __syncthreads();
    float* sOb = reinterpret_cast<float*>(sma + A_STG_B) + wn * (128 * OLD);
    #pragma unroll
    for (int mi = 0; mi < 2; mi++)
        #pragma unroll
        for (int no = 0; no < 8; no++) {
            int row = wm * 32 + mi * 16 + (lane >> 2);
            int col = no * 8 + (lane & 3) * 2;
            *reinterpret_cast<float2*>(&sOb[row * OLD + col]) =
                make_float2(oacc[mi][no][0], oacc[mi][no][1]);
            *reinterpret_cast<float2*>(&sOb[(row + 8) * OLD + col]) =
                make_float2(oacc[mi][no][2], oacc[mi][no][3]);
        }
    __syncthreads();

    // softmax over dk=64; 8 warps x 16 rows
    float* p0buf = reinterpret_cast<float*>(sma + A_STG_B);
    float* p1buf = p0buf + 128 * OLD;
    #pragma unroll
    for (int i = 0; i < 16; i++) {
        int r = wid * 16 + i;
        float v0 = p0buf[r * OLD + lane]      + p1buf[r * OLD + lane];
        float v1 = p0buf[r * OLD + lane + 32] + p1buf[r * OLD + lane + 32];
        float mx = fmaxf(v0, v1);
        #pragma unroll
        for (int o = 16; o > 0; o >>= 1)
            mx = fmaxf(mx, __shfl_xor_sync(0xffffffffu, mx, o));
        float e0 = __expf(v0 - mx), e1 = __expf(v1 - mx);
        float s = e0 + e1;
        #pragma unroll
        for (int o = 16; o > 0; o >>= 1) s += __shfl_xor_sync(0xffffffffu, s, o);
        float inv = 1.0f / s;
        float q0 = e0 * inv, q1 = e1 * inv;
        size_t g = base + (size_t)(s0 + r) * DK;
        bf16 h0 = __float2bfloat16(q0), h1 = __float2bfloat16(q1);
        Mhi[g + lane]      = h0;
        Mhi[g + lane + 32] = h1;
        Mlo[g + lane]      = __float2bfloat16(q0 - __bfloat162float(h0));
        Mlo[g + lane + 32] = __float2bfloat16(q1 - __bfloat162float(h1));
    }
}

// ===========================================================================
// Launch
// ===========================================================================
extern "C" void kernel_launch(void* const* d_in, const int* in_sizes, int n_in,
                              void* d_out, int out_size)
{
    const float* x  = (const float*)d_in[0];
    const float* Wq = (const float*)d_in[1];
    const float* bq = (const float*)d_in[2];
    const float* Wk = (const float*)d_in[3];
    const float* bk = (const float*)d_in[4];
    const float* Wv = (const float*)d_in[5];
    const float* bv = (const float*)d_in[6];
    const float* Wo = (const float*)d_in[7];
    const float* bo = (const float*)d_in[8];
    const float* Wf = (const float*)d_in[9];
    const float* bf_ = (const float*)d_in[10];
    float* out = (float*)d_out;

    bf16 *xhi, *xlo, *Whi, *Wlo, *Qhi, *Qlo, *Khi, *Klo, *Vhi, *Vlo, *Mhi, *Mlo, *Hhi, *Hlo;
    cudaGetSymbolAddress((void**)&xhi, g_xhi); cudaGetSymbolAddress((void**)&xlo, g_xlo);
    cudaGetSymbolAddress((void**)&Whi, g_Whi); cudaGetSymbolAddress((void**)&Wlo, g_Wlo);
    cudaGetSymbolAddress((void**)&Qhi, g_Qhi); cudaGetSymbolAddress((void**)&Qlo, g_Qlo);
    cudaGetSymbolAddress((void**)&Khi, g_Khi); cudaGetSymbolAddress((void**)&Klo, g_Klo);
    cudaGetSymbolAddress((void**)&Vhi, g_Vhi); cudaGetSymbolAddress((void**)&Vlo, g_Vlo);
    cudaGetSymbolAddress((void**)&Mhi, g_Mhi); cudaGetSymbolAddress((void**)&Mlo, g_Mlo);
    cudaGetSymbolAddress((void**)&Hhi, g_Hhi); cudaGetSymbolAddress((void**)&Hlo, g_Hlo);

    cudaFuncSetAttribute(mma_gemm, cudaFuncAttributeMaxDynamicSharedMemorySize, GEMM_SMEM);
    cudaFuncSetAttribute(qkv_gemm, cudaFuncAttributeMaxDynamicSharedMemorySize, GEMM_SMEM);
    cudaFuncSetAttribute(attn_mma, cudaFuncAttributeMaxDynamicSharedMemorySize, ATTN_SMEM);

    int n4tot = N4X + 5 * N4W;
    cvt_all<<<(n4tot + 255)/256, 256>>>(x, Wq, Wk, Wv, Wo, Wf, xhi, xlo, Whi, Wlo);

    dim3 qgrid(DM/64, MROWS/128, 3);
    qkv_gemm<<<qgrid, 256, GEMM_SMEM>>>(xhi, xlo, Whi, Wlo, bq, bk, bv,
                                        Qhi, Qlo, Khi, Klo, Vhi, Vlo);

    dim3 agrid(SEQ/128, BD*NH);
    attn_mma<<<agrid, 256, ATTN_SMEM>>>(Qhi, Qlo, Khi, Klo, Vhi, Vlo, Mhi, Mlo);

    const int WN = DM * DM;
    dim3 ggrid(DM/64, MROWS/128);
    mma_gemm<<<ggrid, 256, GEMM_SMEM>>>(Mhi, Mlo, Whi+3*(size_t)WN, Wlo+3*(size_t)WN, bo, nullptr, Hhi, Hlo);
    mma_gemm<<<ggrid, 256, GEMM_SMEM>>>(Hhi, Hlo, Whi+4*(size_t)WN, Wlo+4*(size_t)WN, bf_, out, nullptr, nullptr);
}